// round 3
// baseline (speedup 1.0000x reference)
#include <cuda_runtime.h>
#include <cuda_bf16.h>

#define NB 4
#define NT 96
#define NN 512
#define NC 514
#define EPSF 1e-8f
#define CPB 128           // CTAs per batch
#define RPC 4             // rows per CTA per step
#define THREADS 256
#define GRID (NB*CPB)
#define ROWP 516          // smem row pitch (floats), 8B-aligned
#define CHUNKS 257        // 8B chunks per 514-float row

__device__ float g_S[2][NB][NN];
__device__ float g_I[2][NB][NN];
__device__ float g_R[2][NB][NN];
__device__ unsigned int g_ctr[NB*NT];

__global__ void ssir_init() {
    int i = threadIdx.x + blockIdx.x * blockDim.x;
    if (i < NB*NT) g_ctr[i] = 0u;
}

__device__ __forceinline__ void cp_async8(float* dst, const float* src) {
    unsigned int d = (unsigned int)__cvta_generic_to_shared(dst);
    asm volatile("cp.async.ca.shared.global [%0], [%1], 8;" :: "r"(d), "l"(src));
}
#define CP_COMMIT() asm volatile("cp.async.commit_group;")
#define CP_WAIT1()  asm volatile("cp.async.wait_group 1;" ::: "memory")
#define CP_WAIT0()  asm volatile("cp.async.wait_group 0;" ::: "memory")

__global__ void __launch_bounds__(THREADS, 4)
ssir_main(const float* __restrict__ x0, const float* __restrict__ params,
          float* __restrict__ out) {
    const int tid  = threadIdx.x;
    const int warp = tid >> 5;
    const int lane = tid & 31;
    const int b    = blockIdx.x / CPB;
    const int ci   = blockIdx.x % CPB;
    const int n0   = ci * RPC;

    __shared__ float sP[2][RPC][ROWP];   // double-buffered param rows
    __shared__ float sI[NN];
    __shared__ float sBG[RPC][2];
    __shared__ float sSum[8][RPC];
    __shared__ float sDot[8][RPC];

    float* out_view = out;
    float* out_epi  = out + (size_t)NB * NT * NN * 3;
    const float* x0b = x0 + (size_t)b * NN * 3;

    // Prologue: prefetch step 0 into buffer 0
    {
        const size_t rb = (size_t)(b * NT + 0) * NN + n0;
        for (int i = tid; i < RPC * CHUNKS; i += THREADS) {
            int r = i / CHUNKS, c = i - r * CHUNKS;
            cp_async8(&sP[0][r][2 * c], params + (rb + r) * NC + 2 * c);
        }
        CP_COMMIT();
    }

    for (int t = 0; t < NT; ++t) {
        const int buf = t & 1;
        const size_t rowbase = (size_t)(b * NT + t) * NN + n0;

        // ---- Issue prefetch for step t+1 (in flight across this whole step) ----
        if (t + 1 < NT) {
            const size_t rb = rowbase + NN;   // (b*NT + t+1)*NN + n0
            #pragma unroll
            for (int i = tid; i < RPC * CHUNKS; i += THREADS) {
                int r = i / CHUNKS, c = i - r * CHUNKS;
                cp_async8(&sP[buf ^ 1][r][2 * c], params + (rb + r) * NC + 2 * c);
            }
            CP_COMMIT();
            CP_WAIT1();     // step t's group done; t+1 stays pending
        } else {
            CP_WAIT0();
        }
        __syncthreads();    // smem params visible to all threads

        // ================= scan-independent work (from smem) =================
        float w0[RPC], w1[RPC];
        #pragma unroll
        for (int r = 0; r < RPC; ++r) {
            w0[r] = __expf(sP[buf][r][2 + tid]);
            w1[r] = __expf(sP[buf][r][2 + 256 + tid]);
        }
        if (tid < RPC * 2) {
            int r = tid >> 1, w = tid & 1;
            float sg = 1.0f / (1.0f + __expf(-sP[buf][r][w]));
            sBG[r][w] = sg;
            __stcs(out_epi + (rowbase + r) * NC + w, sg);
        }

        // Batched 4-row sum reduce
        float s[RPC];
        #pragma unroll
        for (int r = 0; r < RPC; ++r) s[r] = w0[r] + w1[r];
        #pragma unroll
        for (int o = 16; o > 0; o >>= 1) {
            #pragma unroll
            for (int r = 0; r < RPC; ++r) s[r] += __shfl_xor_sync(0xffffffffu, s[r], o);
        }
        if (lane < RPC) sSum[warp][lane] = s[lane];
        __syncthreads();

        float inv[RPC];
        #pragma unroll
        for (int r = 0; r < RPC; ++r) {
            float acc = sSum[0][r];
            #pragma unroll
            for (int k = 1; k < 8; ++k) acc += sSum[k][r];
            inv[r] = __fdividef(1.0f, acc);
        }

        #pragma unroll
        for (int r = 0; r < RPC; ++r) {
            w0[r] *= inv[r];
            w1[r] *= inv[r];
            float* er = out_epi + (rowbase + r) * NC;
            __stcs(er + 2 + tid,       w0[r]);
            __stcs(er + 2 + 256 + tid, w1[r]);
        }

        // ================= barrier: wait for step t-1 =================
        if (t > 0 && tid == 0) {
            volatile unsigned int* vc = &g_ctr[b * NT + (t - 1)];
            while (*vc < (unsigned)CPB) { __nanosleep(32); }
        }
        __syncthreads();
        __threadfence();   // acquire

        // ================= critical chain =================
        const int prev = (t + 1) & 1;
        const int cur  = t & 1;
        float S = 0.f, I = 0.f, R = 0.f;
        if (t == 0) {
            sI[tid]       = x0b[tid * 3 + 1];
            sI[tid + 256] = x0b[(tid + 256) * 3 + 1];
            if (tid < RPC) {
                int n = n0 + tid;
                S = x0b[n * 3 + 0]; I = x0b[n * 3 + 1]; R = x0b[n * 3 + 2];
            }
        } else {
            sI[tid]       = __ldcg(&g_I[prev][b][tid]);
            sI[tid + 256] = __ldcg(&g_I[prev][b][tid + 256]);
            if (tid < RPC) {
                int n = n0 + tid;
                S = __ldcg(&g_S[prev][b][n]);
                I = __ldcg(&g_I[prev][b][n]);
                R = __ldcg(&g_R[prev][b][n]);
            }
        }
        __syncthreads();

        const float i0 = sI[tid], i1 = sI[tid + 256];
        float d[RPC];
        #pragma unroll
        for (int r = 0; r < RPC; ++r) d[r] = w0[r] * i0 + w1[r] * i1;
        #pragma unroll
        for (int o = 16; o > 0; o >>= 1) {
            #pragma unroll
            for (int r = 0; r < RPC; ++r) d[r] += __shfl_xor_sync(0xffffffffu, d[r], o);
        }
        if (lane < RPC) sDot[warp][lane] = d[lane];
        __syncthreads();

        if (tid < RPC) {
            float dot = sDot[0][tid];
            #pragma unroll
            for (int k = 1; k < 8; ++k) dot += sDot[k][tid];

            const float beta  = sBG[tid][0];
            const float gamma = sBG[tid][1];
            const float Np = fmaxf(S + I + R, EPSF);
            const float dS = -beta * S * __fdividef(dot, Np);
            const float dR = gamma * I;
            const float dI = -dS - dR;
            float St = fmaxf(S + dS, 0.0f);
            float It = fmaxf(I + dI, 0.0f);
            float Rt = fmaxf(R + dR, 0.0f);
            const float scale = Np * __fdividef(1.0f, fmaxf(St + It + Rt, EPSF));
            St *= scale; It *= scale; Rt *= scale;

            const int n = n0 + tid;
            __stcg(&g_S[cur][b][n], St);
            __stcg(&g_I[cur][b][n], It);
            __stcg(&g_R[cur][b][n], Rt);
            float* ov = out_view + (rowbase + tid) * 3;
            ov[0] = St; ov[1] = It; ov[2] = Rt;
            __threadfence();   // release
        }
        __syncthreads();
        if (tid == 0) atomicAdd(&g_ctr[b * NT + t], 1u);
        __syncthreads();       // protect sP/sBG reuse (next iter's cp.async overwrite)
    }
}

extern "C" void kernel_launch(void* const* d_in, const int* in_sizes, int n_in,
                              void* d_out, int out_size) {
    const float* x0     = (const float*)d_in[0];
    const float* params = (const float*)d_in[1];
    if (n_in >= 2 && in_sizes[0] > in_sizes[1]) {
        const float* tmp = x0; x0 = params; params = tmp;
    }
    float* out = (float*)d_out;

    ssir_init<<<1, 512>>>();
    ssir_main<<<GRID, THREADS>>>(x0, params, out);
}

// round 4
// speedup vs baseline: 1.2447x; 1.2447x over previous
#include <cuda_runtime.h>
#include <cuda_bf16.h>

#define NB 4
#define NT 96
#define NN 512
#define NC 514
#define EPSF 1e-8f
#define CPB 128           // CTAs per batch
#define RPC 4             // rows per CTA per step
#define THREADS 256
#define GRID (NB*CPB)
#define ROWP 516          // smem row pitch (floats)
#define CHUNKS 257        // 8B chunks per 514-float row
#define NBUF 3            // triple buffer, prefetch distance 2

__device__ float g_S[2][NB][NN];
__device__ float g_I[2][NB][NN];
__device__ float g_R[2][NB][NN];
__device__ unsigned int g_ctr[NB*NT];
__device__ unsigned int g_rdy[NB];

__global__ void ssir_init() {
    int i = threadIdx.x + blockIdx.x * blockDim.x;
    if (i < NB*NT) g_ctr[i] = 0u;
    if (i < NB)    g_rdy[i] = 0u;
}

__device__ __forceinline__ void cp_async8(float* dst, const float* src) {
    unsigned int d = (unsigned int)__cvta_generic_to_shared(dst);
    asm volatile("cp.async.ca.shared.global [%0], [%1], 8;" :: "r"(d), "l"(src));
}
#define CP_COMMIT() asm volatile("cp.async.commit_group;")
#define CP_WAIT2()  asm volatile("cp.async.wait_group 2;" ::: "memory")

__device__ __forceinline__ unsigned int ld_acq(const unsigned int* p) {
    unsigned int v;
    asm volatile("ld.acquire.gpu.global.u32 %0, [%1];" : "=r"(v) : "l"(p));
    return v;
}
__device__ __forceinline__ void red_rel_add1(unsigned int* p) {
    asm volatile("red.release.gpu.global.add.u32 [%0], %1;" :: "l"(p), "r"(1u));
}

__global__ void __launch_bounds__(THREADS, 4)
ssir_main(const float* __restrict__ x0, const float* __restrict__ params,
          float* __restrict__ out) {
    const int tid  = threadIdx.x;
    const int warp = tid >> 5;
    const int lane = tid & 31;
    const int b    = blockIdx.x / CPB;
    const int ci   = blockIdx.x % CPB;
    const int n0   = ci * RPC;

    __shared__ float sP[NBUF][RPC][ROWP];
    __shared__ float sBG[2][RPC][2];
    __shared__ float sSum[8][RPC];
    __shared__ float sDot[8][RPC];

    float* out_view = out;
    float* out_epi  = out + (size_t)NB * NT * NN * 3;
    const float* x0b = x0 + (size_t)b * NN * 3;
    const size_t base0 = (size_t)(b * NT) * NN + n0;

    // ---- Prologue ----
    // issue cp.async for t=0 and t=1 (two groups)
    #pragma unroll 1
    for (int tt = 0; tt < 2; ++tt) {
        const size_t rb = base0 + (size_t)tt * NN;
        for (int i = tid; i < RPC * CHUNKS; i += THREADS) {
            int r = i / CHUNKS, c = i - r * CHUNKS;
            cp_async8(&sP[tt][r][2 * c], params + (rb + r) * NC + 2 * c);
        }
        CP_COMMIT();
    }
    // tid0 seeds state slot 1 with x0 for this CTA's 4 nodes, then releases g_rdy
    if (tid == 0) {
        float st[RPC], it[RPC], rt[RPC];
        #pragma unroll
        for (int r = 0; r < RPC; ++r) {
            int n = n0 + r;
            st[r] = x0b[n * 3 + 0];
            it[r] = x0b[n * 3 + 1];
            rt[r] = x0b[n * 3 + 2];
        }
        __stcg((float4*)&g_S[1][b][n0], make_float4(st[0], st[1], st[2], st[3]));
        __stcg((float4*)&g_I[1][b][n0], make_float4(it[0], it[1], it[2], it[3]));
        __stcg((float4*)&g_R[1][b][n0], make_float4(rt[0], rt[1], rt[2], rt[3]));
        red_rel_add1(&g_rdy[b]);
    }

    for (int t = 0; t < NT; ++t) {
        const int buf = t % NBUF;
        const size_t rowbase = base0 + (size_t)t * NN;

        // ============ STREAM phase: prepare step t (scan-independent) ============
        // issue prefetch for t+2 (distance 2), always commit to keep group count
        if (t + 2 < NT) {
            const size_t rb = rowbase + 2 * NN;
            const int b2 = (t + 2) % NBUF;
            #pragma unroll 1
            for (int i = tid; i < RPC * CHUNKS; i += THREADS) {
                int r = i / CHUNKS, c = i - r * CHUNKS;
                cp_async8(&sP[b2][r][2 * c], params + (rb + r) * NC + 2 * c);
            }
        }
        CP_COMMIT();
        CP_WAIT2();          // buf for step t complete; t+1, t+2 stay in flight
        __syncthreads();

        // exp on adjacent pair per thread (no max shift: params ~ N(0,1))
        float w0[RPC], w1[RPC];
        #pragma unroll
        for (int r = 0; r < RPC; ++r) {
            w0[r] = __expf(sP[buf][r][2 + 2 * tid]);
            w1[r] = __expf(sP[buf][r][3 + 2 * tid]);
        }
        if (tid < RPC * 2) {   // beta/gamma
            int r = tid >> 1, w = tid & 1;
            float sg = 1.0f / (1.0f + __expf(-sP[buf][r][w]));
            sBG[t & 1][r][w] = sg;
            __stcs(out_epi + (rowbase + r) * NC + w, sg);
        }
        // batched 4-row sum reduce
        float s[RPC];
        #pragma unroll
        for (int r = 0; r < RPC; ++r) s[r] = w0[r] + w1[r];
        #pragma unroll
        for (int o = 16; o > 0; o >>= 1) {
            #pragma unroll
            for (int r = 0; r < RPC; ++r) s[r] += __shfl_xor_sync(0xffffffffu, s[r], o);
        }
        if (lane < RPC) sSum[warp][lane] = s[lane];
        __syncthreads();

        #pragma unroll
        for (int r = 0; r < RPC; ++r) {
            float acc = sSum[0][r];
            #pragma unroll
            for (int k = 1; k < 8; ++k) acc += sSum[k][r];
            float inv = __fdividef(1.0f, acc);
            w0[r] *= inv;
            w1[r] *= inv;
            __stcs((float2*)(out_epi + (rowbase + r) * NC + 2 + 2 * tid),
                   make_float2(w0[r], w1[r]));
        }

        // ============ CHAIN phase: the scan ============
        const int prev = (t + 1) & 1;
        const int cur  = t & 1;

        float S[RPC], I[RPC], R[RPC];
        if (tid == 0) {
            // poll for previous step completion
            const unsigned int* cp = (t == 0) ? &g_rdy[b] : &g_ctr[b * NT + (t - 1)];
            while (ld_acq(cp) < (unsigned)CPB) { __nanosleep(40); }
            // own-node state loads (overlap with the dot reduce below)
            #pragma unroll
            for (int r = 0; r < RPC; ++r) {
                int n = n0 + r;
                S[r] = __ldcg(&g_S[prev][b][n]);
                I[r] = __ldcg(&g_I[prev][b][n]);
                R[r] = __ldcg(&g_R[prev][b][n]);
            }
        }
        __syncthreads();   // release the block once tid0 saw the flag

        const float2 iv = __ldcg((const float2*)&g_I[prev][b][2 * tid]);
        float d[RPC];
        #pragma unroll
        for (int r = 0; r < RPC; ++r) d[r] = w0[r] * iv.x + w1[r] * iv.y;
        #pragma unroll
        for (int o = 16; o > 0; o >>= 1) {
            #pragma unroll
            for (int r = 0; r < RPC; ++r) d[r] += __shfl_xor_sync(0xffffffffu, d[r], o);
        }
        if (lane < RPC) sDot[warp][lane] = d[lane];
        __syncthreads();

        if (tid == 0) {
            float St[RPC], It[RPC], Rt[RPC];
            #pragma unroll
            for (int r = 0; r < RPC; ++r) {
                float dot = sDot[0][r];
                #pragma unroll
                for (int k = 1; k < 8; ++k) dot += sDot[k][r];
                const float beta  = sBG[t & 1][r][0];
                const float gamma = sBG[t & 1][r][1];
                const float Np = fmaxf(S[r] + I[r] + R[r], EPSF);
                const float dS = -beta * S[r] * __fdividef(dot, Np);
                const float dR = gamma * I[r];
                const float dI = -dS - dR;
                float Sx = fmaxf(S[r] + dS, 0.0f);
                float Ix = fmaxf(I[r] + dI, 0.0f);
                float Rx = fmaxf(R[r] + dR, 0.0f);
                const float sc = Np * __fdividef(1.0f, fmaxf(Sx + Ix + Rx, EPSF));
                St[r] = Sx * sc; It[r] = Ix * sc; Rt[r] = Rx * sc;
            }
            __stcg((float4*)&g_S[cur][b][n0], make_float4(St[0], St[1], St[2], St[3]));
            __stcg((float4*)&g_I[cur][b][n0], make_float4(It[0], It[1], It[2], It[3]));
            __stcg((float4*)&g_R[cur][b][n0], make_float4(Rt[0], Rt[1], Rt[2], Rt[3]));
            float* ov = out_view + rowbase * 3;
            __stcs((float4*)(ov + 0), make_float4(St[0], It[0], Rt[0], St[1]));
            __stcs((float4*)(ov + 4), make_float4(It[1], Rt[1], St[2], It[2]));
            __stcs((float4*)(ov + 8), make_float4(Rt[2], St[3], It[3], Rt[3]));
            red_rel_add1(&g_ctr[b * NT + t]);   // release covers tid0's own stores
        }
        // no trailing sync needed: next iteration's smem writes are fenced by
        // the syncthreads after CP_WAIT2 / before sSum reuse
    }
}

extern "C" void kernel_launch(void* const* d_in, const int* in_sizes, int n_in,
                              void* d_out, int out_size) {
    const float* x0     = (const float*)d_in[0];
    const float* params = (const float*)d_in[1];
    if (n_in >= 2 && in_sizes[0] > in_sizes[1]) {
        const float* tmp = x0; x0 = params; params = tmp;
    }
    float* out = (float*)d_out;

    ssir_init<<<1, 512>>>();
    ssir_main<<<GRID, THREADS>>>(x0, params, out);
}